// round 3
// baseline (speedup 1.0000x reference)
#include <cuda_runtime.h>
#include <cuda_bf16.h>
#include <math.h>

// ---------------- problem constants ----------------
#define N_   4
#define C1_  256
#define C2_  256
#define CH_  128
#define H_   80
#define W_   80
#define HW_  6400
#define M_   (N_*HW_)      // 25600 pixels total

// ---------------- scratch ----------------
__device__ float g_y1[M_*CH_];     // conv1 out, NHWC [pixel][128]
__device__ float g_y2[M_*C2_];     // conv2 out, NHWC [pixel][256]
__device__ float g_dw[M_*C2_];     // dw+LN+GELU out, NHWC
__device__ float g_xproj[M_*C2_];  // input_proj out, NHWC
__device__ float g_dcn[M_*C2_];    // dcn out, NHWC
__device__ float g_off[M_*18];
__device__ float g_msk[M_*9];

__device__ __forceinline__ float silu_f(float v) { return v / (1.0f + expf(-v)); }

// ================= conv1: 3x3, 256->128, BN+SiLU, reads x NCHW =================
// block = one output row (n, y); 256 threads: tid -> (oc = tid>>1, half = tid&1)
// each thread computes 40 consecutive x positions for its oc.
__global__ __launch_bounds__(256) void p_conv1(const float* __restrict__ x,
                                               const float* __restrict__ w1,
                                               const float* __restrict__ g1,
                                               const float* __restrict__ b1,
                                               const float* __restrict__ m1,
                                               const float* __restrict__ v1) {
    __shared__ float sx[3*82*33];          // [dy][xx(padded 0..81)][ci-chunk 32], pad 33
    int blk = blockIdx.x;
    int n = blk / H_, y = blk % H_;
    int tid = threadIdx.x;
    int oc = tid >> 1;
    int xbase = (tid & 1) * 40;

    float acc[40];
    #pragma unroll
    for (int j = 0; j < 40; j++) acc[j] = 0.0f;

    for (int cc = 0; cc < C1_; cc += 32) {
        __syncthreads();
        // load 3 rows x 82 (padded) x 32 channels
        for (int i = tid; i < 3*82*32; i += 256) {
            int c   = i / (3*82);
            int rem = i % (3*82);
            int dy  = rem / 82;
            int xx  = rem % 82;
            int gy = y + dy - 1;
            int gx = xx - 1;
            float v = 0.0f;
            if (gy >= 0 && gy < H_ && gx >= 0 && gx < W_)
                v = x[(size_t)(n*C1_ + cc + c)*HW_ + gy*W_ + gx];
            sx[(dy*82 + xx)*33 + c] = v;
        }
        __syncthreads();

        for (int ci = 0; ci < 32; ci++) {
            const float* wp = &w1[(size_t)(oc*C1_ + cc + ci)*9];
            float w9[9];
            #pragma unroll
            for (int kk = 0; kk < 9; kk++) w9[kk] = wp[kk];
            #pragma unroll
            for (int dy = 0; dy < 3; dy++) {
                #pragma unroll
                for (int dx = 0; dx < 3; dx++) {
                    float wv = w9[dy*3 + dx];
                    const float* sp = &sx[(dy*82 + xbase + dx)*33 + ci];
                    #pragma unroll
                    for (int j = 0; j < 40; j++)
                        acc[j] = fmaf(sp[j*33], wv, acc[j]);
                }
            }
        }
    }

    float s  = g1[oc] * rsqrtf(v1[oc] + 1e-5f);
    float bb = b1[oc] - m1[oc]*s;
    for (int j = 0; j < 40; j++) {
        float v = acc[j]*s + bb;
        g_y1[(size_t)(n*HW_ + y*W_ + xbase + j)*CH_ + oc] = silu_f(v);
    }
}

// ================= conv2: 1x1, 128->256, BN+SiLU. block per pixel =================
__global__ __launch_bounds__(256) void p_conv2(const float* __restrict__ w2,
                                               const float* __restrict__ g2,
                                               const float* __restrict__ b2,
                                               const float* __restrict__ m2,
                                               const float* __restrict__ v2) {
    int p = blockIdx.x;
    int oc = threadIdx.x;
    const float* a = &g_y1[(size_t)p*CH_];
    const float* w = &w2[(size_t)oc*CH_];
    float acc = 0.0f;
    for (int k = 0; k < CH_; k += 4) {
        float4 av = *(const float4*)&a[k];
        float4 wv = *(const float4*)&w[k];
        acc += av.x*wv.x + av.y*wv.y + av.z*wv.z + av.w*wv.w;
    }
    float s = g2[oc] * rsqrtf(v2[oc] + 1e-5f);
    float v = acc*s + (b2[oc] - m2[oc]*s);
    g_y2[(size_t)p*C2_ + oc] = silu_f(v);
}

// ================= depthwise 3x3 + bias + LayerNorm + GELU =================
__global__ __launch_bounds__(256) void p_dwlngelu(const float* __restrict__ dww,
                                                  const float* __restrict__ dwb,
                                                  const float* __restrict__ lng,
                                                  const float* __restrict__ lnb) {
    int p = blockIdx.x;
    int n = p / HW_, pp = p - n*HW_;
    int y = pp / W_, xx = pp - y*W_;
    int c = threadIdx.x;

    float acc = 0.0f;
    for (int ky = 0; ky < 3; ky++) {
        int gy = y + ky - 1;
        if (gy < 0 || gy >= H_) continue;
        for (int kx = 0; kx < 3; kx++) {
            int gx = xx + kx - 1;
            if (gx < 0 || gx >= W_) continue;
            acc += g_y2[(size_t)(n*HW_ + gy*W_ + gx)*C2_ + c] * dww[c*9 + ky*3 + kx];
        }
    }
    acc += dwb[c];

    __shared__ float red[8], red2[8];
    float v = acc;
    #pragma unroll
    for (int o = 16; o; o >>= 1) v += __shfl_xor_sync(0xffffffffu, v, o);
    if ((c & 31) == 0) red[c >> 5] = v;
    __syncthreads();
    float tot = 0.0f;
    #pragma unroll
    for (int i = 0; i < 8; i++) tot += red[i];
    float mu = tot * (1.0f/256.0f);

    float d = acc - mu;
    float v2 = d*d;
    #pragma unroll
    for (int o = 16; o; o >>= 1) v2 += __shfl_xor_sync(0xffffffffu, v2, o);
    if ((c & 31) == 0) red2[c >> 5] = v2;
    __syncthreads();
    float tot2 = 0.0f;
    #pragma unroll
    for (int i = 0; i < 8; i++) tot2 += red2[i];
    float var = tot2 * (1.0f/256.0f);

    float outv = d * rsqrtf(var + 1e-6f) * lng[c] + lnb[c];
    float gel = 0.5f * outv * (1.0f + erff(outv * 0.70710678118654752f));
    g_dw[(size_t)p*C2_ + c] = gel;
}

// ================= offset + mask heads. block per pixel =================
__global__ __launch_bounds__(256) void p_offmask(const float* __restrict__ offw,
                                                 const float* __restrict__ offb,
                                                 const float* __restrict__ mskw,
                                                 const float* __restrict__ mskb) {
    int p = blockIdx.x;
    int tid = threadIdx.x;
    int warp = tid >> 5, lane = tid & 31;
    __shared__ float sdw[256];
    __shared__ float sres[27];

    sdw[tid] = g_dw[(size_t)p*C2_ + tid];
    __syncthreads();

    // warp w computes rows w, w+8, w+16, w+24 (r<27)
    for (int r = warp; r < 27; r += 8) {
        const float* wr = (r < 18) ? (offw + r*256) : (mskw + (r-18)*256);
        float s = 0.0f;
        for (int c = lane; c < 256; c += 32) s += sdw[c] * wr[c];
        #pragma unroll
        for (int o = 16; o; o >>= 1) s += __shfl_xor_sync(0xffffffffu, s, o);
        if (lane == 0) sres[r] = s;
    }
    __syncthreads();

    if (tid < 18) g_off[(size_t)p*18 + tid] = sres[tid] + offb[tid];
    if (tid == 0) {
        float l[9], mx = -1e30f;
        #pragma unroll
        for (int k = 0; k < 9; k++) { l[k] = sres[18+k] + mskb[k]; mx = fmaxf(mx, l[k]); }
        float se = 0.0f;
        #pragma unroll
        for (int k = 0; k < 9; k++) { l[k] = expf(l[k] - mx); se += l[k]; }
        float inv = 1.0f / se;
        #pragma unroll
        for (int k = 0; k < 9; k++) g_msk[(size_t)p*9 + k] = l[k]*inv;
    }
}

// ================= input_proj: y2 @ in_w.T + in_b. block per pixel =================
__global__ __launch_bounds__(256) void p_inproj(const float* __restrict__ inw,
                                                const float* __restrict__ inb) {
    int p = blockIdx.x;
    int o = threadIdx.x;
    const float* a = &g_y2[(size_t)p*C2_];
    const float* w = &inw[(size_t)o*C2_];
    float acc = 0.0f;
    for (int k = 0; k < C2_; k += 4) {
        float4 av = *(const float4*)&a[k];
        float4 wv = *(const float4*)&w[k];
        acc += av.x*wv.x + av.y*wv.y + av.z*wv.z + av.w*wv.w;
    }
    g_xproj[(size_t)p*C2_ + o] = acc + inb[o];
}

// ================= DCNv3 core, mirrors reference padded-coordinate math =================
__global__ __launch_bounds__(256) void p_dcn() {
    int p = blockIdx.x;
    int n = p / HW_, pp = p - n*HW_;
    int y = pp / W_, xx = pp - y*W_;
    int c = threadIdx.x;

    __shared__ float sw[9][4];
    __shared__ int   sx0[9], sy0[9];
    if (threadIdx.x < 9) {
        int k = threadIdx.x;
        float m  = g_msk[(size_t)p*9 + k];
        float ox = g_off[(size_t)p*18 + 2*k];
        float oy = g_off[(size_t)p*18 + 2*k + 1];
        // padded coords: px = w + (k/3) + ox ; py = h + (k%3) + oy
        float px = (float)xx + (float)(k/3) + ox;
        float py = (float)y  + (float)(k%3) + oy;
        float x0f = floorf(px), y0f = floorf(py);
        float lw = px - x0f, lh = py - y0f;
        sw[k][0] = m * (1.0f - lh) * (1.0f - lw);
        sw[k][1] = m * (1.0f - lh) * lw;
        sw[k][2] = m * lh * (1.0f - lw);
        sw[k][3] = m * lh * lw;
        sx0[k] = (int)x0f;
        sy0[k] = (int)y0f;
    }
    __syncthreads();

    const float* Xb = &g_xproj[(size_t)n * HW_ * C2_];
    float acc = 0.0f;
    for (int k = 0; k < 9; k++) {
        int x0 = sx0[k], y0 = sy0[k];
        #pragma unroll
        for (int t = 0; t < 4; t++) {
            int xi = x0 + (t & 1);
            int yi = y0 + (t >> 1);
            // padded image value is nonzero only for interior: 1..80 (ring & OOB give 0)
            if (xi >= 1 && xi <= W_ && yi >= 1 && yi <= H_) {
                float val = Xb[(size_t)((yi-1)*W_ + (xi-1))*C2_ + c];
                acc = fmaf(sw[k][t], val, acc);
            }
        }
    }
    g_dcn[(size_t)p*C2_ + c] = acc;
}

// ================= output_proj + BN3 + SiLU + residual -> NCHW =================
__global__ __launch_bounds__(256) void p_outproj(const float* __restrict__ outw,
                                                 const float* __restrict__ outb,
                                                 const float* __restrict__ g3,
                                                 const float* __restrict__ b3,
                                                 const float* __restrict__ m3,
                                                 const float* __restrict__ v3,
                                                 const float* __restrict__ xin,
                                                 float* __restrict__ out) {
    int p = blockIdx.x;
    int n = p / HW_, pp = p - n*HW_;
    int o = threadIdx.x;
    const float* a = &g_dcn[(size_t)p*C2_];
    const float* w = &outw[(size_t)o*C2_];
    float acc = 0.0f;
    for (int k = 0; k < C2_; k += 4) {
        float4 av = *(const float4*)&a[k];
        float4 wv = *(const float4*)&w[k];
        acc += av.x*wv.x + av.y*wv.y + av.z*wv.z + av.w*wv.w;
    }
    float z = acc + outb[o];
    float s = g3[o] * rsqrtf(v3[o] + 1e-5f);
    z = z*s + (b3[o] - m3[o]*s);
    z = silu_f(z);
    size_t idx = (size_t)(n*C2_ + o)*HW_ + pp;
    out[idx] = xin[idx] + z;
}

// ---------------- launch ----------------
extern "C" void kernel_launch(void* const* d_in, const int* in_sizes, int n_in,
                              void* d_out, int out_size) {
    const float* x     = (const float*)d_in[0];
    const float* w1    = (const float*)d_in[1];
    const float* g1    = (const float*)d_in[2];
    const float* b1    = (const float*)d_in[3];
    const float* m1    = (const float*)d_in[4];
    const float* v1    = (const float*)d_in[5];
    const float* w2    = (const float*)d_in[6];
    const float* g2    = (const float*)d_in[7];
    const float* b2    = (const float*)d_in[8];
    const float* m2    = (const float*)d_in[9];
    const float* v2    = (const float*)d_in[10];
    const float* dw_w  = (const float*)d_in[11];
    const float* dw_b  = (const float*)d_in[12];
    const float* ln_g  = (const float*)d_in[13];
    const float* ln_b  = (const float*)d_in[14];
    const float* off_w = (const float*)d_in[15];
    const float* off_b = (const float*)d_in[16];
    const float* msk_w = (const float*)d_in[17];
    const float* msk_b = (const float*)d_in[18];
    const float* in_w  = (const float*)d_in[19];
    const float* in_b  = (const float*)d_in[20];
    const float* out_w = (const float*)d_in[21];
    const float* out_b = (const float*)d_in[22];
    const float* g3    = (const float*)d_in[23];
    const float* b3    = (const float*)d_in[24];
    const float* m3    = (const float*)d_in[25];
    const float* v3    = (const float*)d_in[26];
    float* out = (float*)d_out;

    p_conv1<<<N_*H_, 256>>>(x, w1, g1, b1, m1, v1);
    p_conv2<<<M_, 256>>>(w2, g2, b2, m2, v2);
    p_dwlngelu<<<M_, 256>>>(dw_w, dw_b, ln_g, ln_b);
    p_offmask<<<M_, 256>>>(off_w, off_b, msk_w, msk_b);
    p_inproj<<<M_, 256>>>(in_w, in_b);
    p_dcn<<<M_, 256>>>();
    p_outproj<<<M_, 256>>>(out_w, out_b, g3, b3, m3, v3, x, out);
}

// round 5
// speedup vs baseline: 4.0805x; 4.0805x over previous
#include <cuda_runtime.h>
#include <cuda_bf16.h>
#include <math.h>

// ---------------- problem constants ----------------
#define N_   4
#define C1_  256
#define C2_  256
#define CH_  128
#define H_   80
#define W_   80
#define HW_  6400
#define M_   (N_*HW_)      // 25600 pixels total

// ---------------- scratch (referenced ONLY inside device code!) ----------------
__device__ float g_xn[M_*C1_];        // x in NHWC
__device__ float g_w1d[C1_*9*CH_*2];  // conv1 w, [ci][kk][oc] BN-folded, duplicated pairs
__device__ float g_b1f[CH_];
__device__ float g_w2t[CH_*C2_];      // conv2 w transposed [k][o], BN-folded
__device__ float g_b2f[C2_];
__device__ float g_inwt[C2_*C2_];     // in_w transposed [k][o]
__device__ float g_outwt[C2_*C2_];    // out_w transposed [k][o], BN3-folded
__device__ float g_obf[C2_];          // folded output bias
__device__ float g_y1[M_*CH_];        // conv1 out NHWC
__device__ float g_y2[M_*C2_];        // conv2 out NHWC
__device__ float g_dw[M_*C2_];        // dw+LN+GELU out NHWC
__device__ float g_xproj[M_*C2_];     // input_proj out NHWC
__device__ float g_dcn[M_*C2_];       // dcn out NHWC
__device__ float g_off[M_*18];
__device__ float g_msk[M_*9];

__device__ __forceinline__ float silu_f(float v) { return v / (1.0f + expf(-v)); }

// ---- f32x2 helpers ----
typedef unsigned long long ull;
__device__ __forceinline__ ull pk2(float lo, float hi) {
    ull r; asm("mov.b64 %0, {%1, %2};" : "=l"(r) : "f"(lo), "f"(hi)); return r;
}
__device__ __forceinline__ void fma2(ull& d, ull a, ull b) {
    asm("fma.rn.f32x2 %0, %1, %2, %0;" : "+l"(d) : "l"(a), "l"(b));
}
__device__ __forceinline__ float2 upk2(ull v) {
    float2 r; asm("mov.b64 {%0, %1}, %2;" : "=f"(r.x), "=f"(r.y) : "l"(v)); return r;
}

// ================= pack kernels =================
__global__ void pk_w1(const float* __restrict__ w1, const float* __restrict__ g1,
                      const float* __restrict__ b1, const float* __restrict__ m1,
                      const float* __restrict__ v1) {
    int i = blockIdx.x * blockDim.x + threadIdx.x;
    if (i >= C1_*9*CH_) return;
    int oc = i & (CH_-1);
    int kidx = i >> 7;          // ci*9 + kk
    int ci = kidx / 9, kk = kidx - ci*9;
    float s = g1[oc] * rsqrtf(v1[oc] + 1e-5f);
    float val = w1[(size_t)(oc*C1_ + ci)*9 + kk] * s;
    g_w1d[(size_t)i*2]     = val;
    g_w1d[(size_t)i*2 + 1] = val;
    if (i < CH_) g_b1f[i] = b1[i] - m1[i]*s;
}

__global__ void pk_lin(const float* __restrict__ w2, const float* __restrict__ g2,
                       const float* __restrict__ b2, const float* __restrict__ m2,
                       const float* __restrict__ v2, const float* __restrict__ inw,
                       const float* __restrict__ outw, const float* __restrict__ outb,
                       const float* __restrict__ g3, const float* __restrict__ b3,
                       const float* __restrict__ m3, const float* __restrict__ v3) {
    int i = blockIdx.x * blockDim.x + threadIdx.x;
    if (i >= C2_*C2_) return;
    int o = i & 255, k = i >> 8;
    g_inwt[i] = inw[(size_t)o*C2_ + k];
    float s3 = g3[o] * rsqrtf(v3[o] + 1e-5f);
    g_outwt[i] = outw[(size_t)o*C2_ + k] * s3;
    if (k < CH_) {
        float s2 = g2[o] * rsqrtf(v2[o] + 1e-5f);
        g_w2t[(size_t)k*C2_ + o] = w2[(size_t)o*CH_ + k] * s2;
    }
    if (i < C2_) {
        float s2 = g2[i] * rsqrtf(v2[i] + 1e-5f);
        g_b2f[i] = b2[i] - m2[i]*s2;
        float s3b = g3[i] * rsqrtf(v3[i] + 1e-5f);
        g_obf[i] = outb[i]*s3b + b3[i] - m3[i]*s3b;
    }
}

// ================= NCHW -> NHWC transpose =================
__global__ void k_tr(const float* __restrict__ x) {
    __shared__ float tile[32][33];
    int n  = blockIdx.z;
    int c0 = blockIdx.y * 32, p0 = blockIdx.x * 32;
    for (int r = threadIdx.y; r < 32; r += 8)
        tile[r][threadIdx.x] = x[(size_t)(n*C1_ + c0 + r)*HW_ + p0 + threadIdx.x];
    __syncthreads();
    for (int r = threadIdx.y; r < 32; r += 8)
        g_xn[(size_t)(n*HW_ + p0 + r)*C1_ + c0 + threadIdx.x] = tile[threadIdx.x][r];
}

// ================= conv1: 3x3 256->128, BN+SiLU, f32x2, NHWC =================
// block: 8x8 px tile, 128 oc. 256 threads: py = tid>>5, ocg = tid&31 (4 oc each)
__global__ __launch_bounds__(256) void c1_fast() {
    __shared__ float sIn[100*33];           // [(hy*10+hx)][ci chunk 32], pad 33
    int tid = threadIdx.x;
    int n = blockIdx.z;
    int by = blockIdx.y * 8, bx = blockIdx.x * 8;
    int py  = tid >> 5;
    int ocg = tid & 31;                     // oc = ocg*4 .. +3

    ull acc[4][4];                          // [oc][px pair]
    #pragma unroll
    for (int o = 0; o < 4; o++)
        #pragma unroll
        for (int j = 0; j < 4; j++) acc[o][j] = 0ull;

    for (int cc = 0; cc < C1_; cc += 32) {
        __syncthreads();
        #pragma unroll 4
        for (int i = tid; i < 3200; i += 256) {
            int c = i & 31, p = i >> 5;
            int hy = p / 10, hx = p - hy*10;
            int gy = by + hy - 1, gx = bx + hx - 1;
            float v = 0.0f;
            if (gy >= 0 && gy < H_ && gx >= 0 && gx < W_)
                v = g_xn[(size_t)(n*HW_ + gy*W_ + gx)*C1_ + cc + c];
            sIn[p*33 + c] = v;
        }
        __syncthreads();

        #pragma unroll 1
        for (int ci = 0; ci < 32; ci++) {
            #pragma unroll
            for (int ky = 0; ky < 3; ky++) {
                #pragma unroll
                for (int kx = 0; kx < 3; kx++) {
                    const float* sp = &sIn[((py + ky)*10 + kx)*33 + ci];
                    ull ip[4];
                    #pragma unroll
                    for (int j = 0; j < 4; j++)
                        ip[j] = pk2(sp[(2*j)*33], sp[(2*j+1)*33]);
                    const ulonglong2* wp = reinterpret_cast<const ulonglong2*>(
                        &g_w1d[((size_t)((cc + ci)*9 + ky*3 + kx)*CH_ + ocg*4)*2]);
                    ulonglong2 w01 = wp[0], w23 = wp[1];
                    #pragma unroll
                    for (int j = 0; j < 4; j++) {
                        fma2(acc[0][j], ip[j], w01.x);
                        fma2(acc[1][j], ip[j], w01.y);
                        fma2(acc[2][j], ip[j], w23.x);
                        fma2(acc[3][j], ip[j], w23.y);
                    }
                }
            }
        }
    }

    int gy = by + py;
    float bia[4];
    #pragma unroll
    for (int o = 0; o < 4; o++) bia[o] = g_b1f[ocg*4 + o];
    #pragma unroll
    for (int j = 0; j < 4; j++) {
        float4 r0, r1;
        float2 t;
        t = upk2(acc[0][j]); r0.x = silu_f(t.x + bia[0]); r1.x = silu_f(t.y + bia[0]);
        t = upk2(acc[1][j]); r0.y = silu_f(t.x + bia[1]); r1.y = silu_f(t.y + bia[1]);
        t = upk2(acc[2][j]); r0.z = silu_f(t.x + bia[2]); r1.z = silu_f(t.y + bia[2]);
        t = upk2(acc[3][j]); r0.w = silu_f(t.x + bia[3]); r1.w = silu_f(t.y + bia[3]);
        size_t base = (size_t)(n*HW_ + gy*W_ + bx)*CH_ + ocg*4;
        *(float4*)&g_y1[base + (size_t)(2*j)*CH_]   = r0;
        *(float4*)&g_y1[base + (size_t)(2*j+1)*CH_] = r1;
    }
}

// ================= GEMM: out[M,256] = A[M,KD] @ B[KD,256] (+epilogue) =================
// BM=64, BN=128, BK=16, 256 threads, thread tile 4m x 8n (f32x2 pairs along n)
// All scratch operands resolved inside device code (NEVER passed from host).
// MODE 0 (conv2):  A=g_y1  B=g_w2t  bias=g_b2f  SiLU -> g_y2
// MODE 1 (inproj): A=g_y2  B=g_inwt bias=ext    none -> g_xproj
// MODE 2 (outproj):A=g_dcn B=g_outwt bias=g_obf SiLU+resid -> ext out (NCHW)
template<int KD, int MODE>
__global__ __launch_bounds__(256) void gm(const float* __restrict__ bias_ext,
                                          float* __restrict__ out_ext,
                                          const float* __restrict__ resid_ext) {
    const float* A    = (MODE == 0) ? g_y1  : (MODE == 1 ? g_y2   : g_dcn);
    const float* B    = (MODE == 0) ? g_w2t : (MODE == 1 ? g_inwt : g_outwt);
    const float* bias = (MODE == 0) ? g_b2f : (MODE == 1 ? bias_ext : g_obf);
    float* C          = (MODE == 0) ? g_y2  : (MODE == 1 ? g_xproj : out_ext);

    __shared__ float As[16][68];
    __shared__ float Bs[16][136];
    int tid = threadIdx.x;
    int tx = tid & 15, ty = tid >> 4;
    int m0 = blockIdx.x * 64, n0 = blockIdx.y * 128;

    ull acc[4][4];
    #pragma unroll
    for (int i = 0; i < 4; i++)
        #pragma unroll
        for (int j = 0; j < 4; j++) acc[i][j] = 0ull;

    int ar = tid >> 2, ak = (tid & 3) * 4;
    int bk = tid >> 4, bn = (tid & 15) * 8;

    for (int k0 = 0; k0 < KD; k0 += 16) {
        float4 av = *(const float4*)&A[(size_t)(m0 + ar)*KD + k0 + ak];
        const float4* bp = (const float4*)&B[(size_t)(k0 + bk)*256 + n0 + bn];
        float4 bv0 = bp[0], bv1 = bp[1];
        As[ak+0][ar] = av.x; As[ak+1][ar] = av.y;
        As[ak+2][ar] = av.z; As[ak+3][ar] = av.w;
        *(float4*)&Bs[bk][bn]     = bv0;
        *(float4*)&Bs[bk][bn + 4] = bv1;
        __syncthreads();
        #pragma unroll
        for (int k = 0; k < 16; k++) {
            float4 a4 = *(const float4*)&As[k][ty*4];
            ull b[4];
            #pragma unroll
            for (int j = 0; j < 4; j++)
                b[j] = *(const ull*)&Bs[k][tx*8 + 2*j];
            ull ad0 = pk2(a4.x, a4.x), ad1 = pk2(a4.y, a4.y);
            ull ad2 = pk2(a4.z, a4.z), ad3 = pk2(a4.w, a4.w);
            #pragma unroll
            for (int j = 0; j < 4; j++) {
                fma2(acc[0][j], ad0, b[j]);
                fma2(acc[1][j], ad1, b[j]);
                fma2(acc[2][j], ad2, b[j]);
                fma2(acc[3][j], ad3, b[j]);
            }
        }
        __syncthreads();
    }

    #pragma unroll
    for (int i = 0; i < 4; i++) {
        int m = m0 + ty*4 + i;
        int nimg = m / HW_;
        int pp   = m - nimg*HW_;
        #pragma unroll
        for (int j = 0; j < 4; j++) {
            float2 v = upk2(acc[i][j]);
            int nn = n0 + tx*8 + 2*j;
            float r0 = v.x + bias[nn];
            float r1 = v.y + bias[nn+1];
            if (MODE == 0 || MODE == 2) { r0 = silu_f(r0); r1 = silu_f(r1); }
            if (MODE <= 1) {
                C[(size_t)m*256 + nn]     = r0;
                C[(size_t)m*256 + nn + 1] = r1;
            } else {
                size_t base = (size_t)(nimg*256 + nn)*HW_ + pp;
                C[base]       = resid_ext[base]       + r0;
                C[base + HW_] = resid_ext[base + HW_] + r1;
            }
        }
    }
}

// ================= depthwise 3x3 + bias + LayerNorm + GELU =================
__global__ __launch_bounds__(256) void p_dwlngelu(const float* __restrict__ dww,
                                                  const float* __restrict__ dwb,
                                                  const float* __restrict__ lng,
                                                  const float* __restrict__ lnb) {
    int p = blockIdx.x;
    int n = p / HW_, pp = p - n*HW_;
    int y = pp / W_, xx = pp - y*W_;
    int c = threadIdx.x;

    float acc = 0.0f;
    for (int ky = 0; ky < 3; ky++) {
        int gy = y + ky - 1;
        if (gy < 0 || gy >= H_) continue;
        for (int kx = 0; kx < 3; kx++) {
            int gx = xx + kx - 1;
            if (gx < 0 || gx >= W_) continue;
            acc += g_y2[(size_t)(n*HW_ + gy*W_ + gx)*C2_ + c] * dww[c*9 + ky*3 + kx];
        }
    }
    acc += dwb[c];

    __shared__ float red[8], red2[8];
    float v = acc;
    #pragma unroll
    for (int o = 16; o; o >>= 1) v += __shfl_xor_sync(0xffffffffu, v, o);
    if ((c & 31) == 0) red[c >> 5] = v;
    __syncthreads();
    float tot = 0.0f;
    #pragma unroll
    for (int i = 0; i < 8; i++) tot += red[i];
    float mu = tot * (1.0f/256.0f);

    float d = acc - mu;
    float v2 = d*d;
    #pragma unroll
    for (int o = 16; o; o >>= 1) v2 += __shfl_xor_sync(0xffffffffu, v2, o);
    if ((c & 31) == 0) red2[c >> 5] = v2;
    __syncthreads();
    float tot2 = 0.0f;
    #pragma unroll
    for (int i = 0; i < 8; i++) tot2 += red2[i];
    float var = tot2 * (1.0f/256.0f);

    float outv = d * rsqrtf(var + 1e-6f) * lng[c] + lnb[c];
    float gel = 0.5f * outv * (1.0f + erff(outv * 0.70710678118654752f));
    g_dw[(size_t)p*C2_ + c] = gel;
}

// ================= offset + mask heads =================
__global__ __launch_bounds__(256) void p_offmask(const float* __restrict__ offw,
                                                 const float* __restrict__ offb,
                                                 const float* __restrict__ mskw,
                                                 const float* __restrict__ mskb) {
    int p = blockIdx.x;
    int tid = threadIdx.x;
    int warp = tid >> 5, lane = tid & 31;
    __shared__ float sdw[256];
    __shared__ float sres[27];

    sdw[tid] = g_dw[(size_t)p*C2_ + tid];
    __syncthreads();

    for (int r = warp; r < 27; r += 8) {
        const float* wr = (r < 18) ? (offw + r*256) : (mskw + (r-18)*256);
        float s = 0.0f;
        for (int c = lane; c < 256; c += 32) s += sdw[c] * wr[c];
        #pragma unroll
        for (int o = 16; o; o >>= 1) s += __shfl_xor_sync(0xffffffffu, s, o);
        if (lane == 0) sres[r] = s;
    }
    __syncthreads();

    if (tid < 18) g_off[(size_t)p*18 + tid] = sres[tid] + offb[tid];
    if (tid == 0) {
        float l[9], mx = -1e30f;
        #pragma unroll
        for (int k = 0; k < 9; k++) { l[k] = sres[18+k] + mskb[k]; mx = fmaxf(mx, l[k]); }
        float se = 0.0f;
        #pragma unroll
        for (int k = 0; k < 9; k++) { l[k] = expf(l[k] - mx); se += l[k]; }
        float inv = 1.0f / se;
        #pragma unroll
        for (int k = 0; k < 9; k++) g_msk[(size_t)p*9 + k] = l[k]*inv;
    }
}

// ================= DCNv3 core =================
__global__ __launch_bounds__(256) void p_dcn() {
    int p = blockIdx.x;
    int n = p / HW_, pp = p - n*HW_;
    int y = pp / W_, xx = pp - y*W_;
    int c = threadIdx.x;

    __shared__ float sw[9][4];
    __shared__ int   sx0[9], sy0[9];
    if (threadIdx.x < 9) {
        int k = threadIdx.x;
        float m  = g_msk[(size_t)p*9 + k];
        float ox = g_off[(size_t)p*18 + 2*k];
        float oy = g_off[(size_t)p*18 + 2*k + 1];
        float px = (float)xx + (float)(k/3) + ox;     // padded coords
        float py = (float)y  + (float)(k%3) + oy;
        float x0f = floorf(px), y0f = floorf(py);
        float lw = px - x0f, lh = py - y0f;
        sw[k][0] = m * (1.0f - lh) * (1.0f - lw);
        sw[k][1] = m * (1.0f - lh) * lw;
        sw[k][2] = m * lh * (1.0f - lw);
        sw[k][3] = m * lh * lw;
        sx0[k] = (int)x0f;
        sy0[k] = (int)y0f;
    }
    __syncthreads();

    const float* Xb = &g_xproj[(size_t)n * HW_ * C2_];
    float acc = 0.0f;
    for (int k = 0; k < 9; k++) {
        int x0 = sx0[k], y0 = sy0[k];
        #pragma unroll
        for (int t = 0; t < 4; t++) {
            int xi = x0 + (t & 1);
            int yi = y0 + (t >> 1);
            if (xi >= 1 && xi <= W_ && yi >= 1 && yi <= H_) {
                float val = Xb[(size_t)((yi-1)*W_ + (xi-1))*C2_ + c];
                acc = fmaf(sw[k][t], val, acc);
            }
        }
    }
    g_dcn[(size_t)p*C2_ + c] = acc;
}

// ---------------- launch ----------------
extern "C" void kernel_launch(void* const* d_in, const int* in_sizes, int n_in,
                              void* d_out, int out_size) {
    const float* x     = (const float*)d_in[0];
    const float* w1    = (const float*)d_in[1];
    const float* g1    = (const float*)d_in[2];
    const float* b1    = (const float*)d_in[3];
    const float* m1    = (const float*)d_in[4];
    const float* v1    = (const float*)d_in[5];
    const float* w2    = (const float*)d_in[6];
    const float* g2    = (const float*)d_in[7];
    const float* b2    = (const float*)d_in[8];
    const float* m2    = (const float*)d_in[9];
    const float* v2    = (const float*)d_in[10];
    const float* dw_w  = (const float*)d_in[11];
    const float* dw_b  = (const float*)d_in[12];
    const float* ln_g  = (const float*)d_in[13];
    const float* ln_b  = (const float*)d_in[14];
    const float* off_w = (const float*)d_in[15];
    const float* off_b = (const float*)d_in[16];
    const float* msk_w = (const float*)d_in[17];
    const float* msk_b = (const float*)d_in[18];
    const float* in_w  = (const float*)d_in[19];
    const float* in_b  = (const float*)d_in[20];
    const float* out_w = (const float*)d_in[21];
    const float* out_b = (const float*)d_in[22];
    const float* g3    = (const float*)d_in[23];
    const float* b3    = (const float*)d_in[24];
    const float* m3    = (const float*)d_in[25];
    const float* v3    = (const float*)d_in[26];
    float* out = (float*)d_out;

    pk_w1<<<(C1_*9*CH_ + 255)/256, 256>>>(w1, g1, b1, m1, v1);
    pk_lin<<<(C2_*C2_ + 255)/256, 256>>>(w2, g2, b2, m2, v2, in_w, out_w, out_b,
                                         g3, b3, m3, v3);
    k_tr<<<dim3(HW_/32, C1_/32, N_), dim3(32, 8)>>>(x);
    c1_fast<<<dim3(W_/8, H_/8, N_), 256>>>();
    gm<128, 0><<<dim3(M_/64, 2), 256>>>(nullptr, nullptr, nullptr);
    p_dwlngelu<<<M_, 256>>>(dw_w, dw_b, ln_g, ln_b);
    p_offmask<<<M_, 256>>>(off_w, off_b, msk_w, msk_b);
    gm<256, 1><<<dim3(M_/64, 2), 256>>>(in_b, nullptr, nullptr);
    p_dcn<<<M_, 256>>>();
    gm<256, 2><<<dim3(M_/64, 2), 256>>>(nullptr, out, x);
}

// round 7
// speedup vs baseline: 4.3211x; 1.0590x over previous
#include <cuda_runtime.h>
#include <cuda_bf16.h>
#include <math.h>
#include <stdint.h>

// ---------------- problem constants ----------------
#define N_   4
#define C1_  256
#define C2_  256
#define CH_  128
#define H_   80
#define W_   80
#define HW_  6400
#define M_   (N_*HW_)      // 25600 pixels total
#define PL   124           // smem plane stride (floats) per ci: 10 rows x 12 + pad

// ---------------- scratch (referenced ONLY inside device code!) ----------------
__device__ float g_xn[M_*C1_];        // x in NHWC
__device__ float g_w1d[C1_*9*CH_*2];  // conv1 w, [ci][kk][oc] BN-folded, duplicated pairs
__device__ float g_b1f[CH_];
__device__ float g_w2t[CH_*C2_];      // conv2 w transposed [k][o], BN-folded
__device__ float g_b2f[C2_];
__device__ float g_inwt[C2_*C2_];     // in_w transposed [k][o]
__device__ float g_outwt[C2_*C2_];    // out_w transposed [k][o], BN3-folded
__device__ float g_obf[C2_];          // folded output bias
__device__ float g_y1[M_*CH_];        // conv1 out NHWC
__device__ float g_y2[M_*C2_];        // conv2 out NHWC
__device__ float g_dw[M_*C2_];        // dw+LN+GELU out NHWC
__device__ float g_xproj[M_*C2_];     // input_proj out NHWC
__device__ float g_dcn[M_*C2_];       // dcn out NHWC
__device__ float g_off[M_*18];
__device__ float g_msk[M_*9];

__device__ __forceinline__ float silu_f(float v) { return v / (1.0f + expf(-v)); }

// ---- f32x2 helpers ----
typedef unsigned long long ull;
__device__ __forceinline__ ull pk2(float lo, float hi) {
    ull r; asm("mov.b64 %0, {%1, %2};" : "=l"(r) : "f"(lo), "f"(hi)); return r;
}
__device__ __forceinline__ void fma2(ull& d, ull a, ull b) {
    asm("fma.rn.f32x2 %0, %1, %2, %0;" : "+l"(d) : "l"(a), "l"(b));
}
__device__ __forceinline__ float2 upk2(ull v) {
    float2 r; asm("mov.b64 {%0, %1}, %2;" : "=f"(r.x), "=f"(r.y) : "l"(v)); return r;
}
__device__ __forceinline__ uint32_t smem_u32(const void* p) {
    uint32_t a;
    asm("{ .reg .u64 t; cvta.to.shared.u64 t, %1; cvt.u32.u64 %0, t; }" : "=r"(a) : "l"(p));
    return a;
}
__device__ __forceinline__ void cp4(uint32_t sa, const float* ga, uint32_t sz) {
    asm volatile("cp.async.ca.shared.global [%0], [%1], 4, %2;\n"
                 :: "r"(sa), "l"(ga), "r"(sz));
}

// ================= pack kernels =================
__global__ void pk_w1(const float* __restrict__ w1, const float* __restrict__ g1,
                      const float* __restrict__ b1, const float* __restrict__ m1,
                      const float* __restrict__ v1) {
    int i = blockIdx.x * blockDim.x + threadIdx.x;
    if (i >= C1_*9*CH_) return;
    int oc = i & (CH_-1);
    int kidx = i >> 7;          // ci*9 + kk
    int ci = kidx / 9, kk = kidx - ci*9;
    float s = g1[oc] * rsqrtf(v1[oc] + 1e-5f);
    float val = w1[(size_t)(oc*C1_ + ci)*9 + kk] * s;
    g_w1d[(size_t)i*2]     = val;
    g_w1d[(size_t)i*2 + 1] = val;
    if (i < CH_) g_b1f[i] = b1[i] - m1[i]*s;
}

__global__ void pk_lin(const float* __restrict__ w2, const float* __restrict__ g2,
                       const float* __restrict__ b2, const float* __restrict__ m2,
                       const float* __restrict__ v2, const float* __restrict__ inw,
                       const float* __restrict__ outw, const float* __restrict__ outb,
                       const float* __restrict__ g3, const float* __restrict__ b3,
                       const float* __restrict__ m3, const float* __restrict__ v3) {
    int i = blockIdx.x * blockDim.x + threadIdx.x;
    if (i >= C2_*C2_) return;
    int o = i & 255, k = i >> 8;
    g_inwt[i] = inw[(size_t)o*C2_ + k];
    float s3 = g3[o] * rsqrtf(v3[o] + 1e-5f);
    g_outwt[i] = outw[(size_t)o*C2_ + k] * s3;
    if (k < CH_) {
        float s2 = g2[o] * rsqrtf(v2[o] + 1e-5f);
        g_w2t[(size_t)k*C2_ + o] = w2[(size_t)o*CH_ + k] * s2;
    }
    if (i < C2_) {
        float s2 = g2[i] * rsqrtf(v2[i] + 1e-5f);
        g_b2f[i] = b2[i] - m2[i]*s2;
        float s3b = g3[i] * rsqrtf(v3[i] + 1e-5f);
        g_obf[i] = outb[i]*s3b + b3[i] - m3[i]*s3b;
    }
}

// ================= NCHW -> NHWC transpose =================
__global__ void k_tr(const float* __restrict__ x) {
    __shared__ float tile[32][33];
    int n  = blockIdx.z;
    int c0 = blockIdx.y * 32, p0 = blockIdx.x * 32;
    for (int r = threadIdx.y; r < 32; r += 8)
        tile[r][threadIdx.x] = x[(size_t)(n*C1_ + c0 + r)*HW_ + p0 + threadIdx.x];
    __syncthreads();
    for (int r = threadIdx.y; r < 32; r += 8)
        g_xn[(size_t)(n*HW_ + p0 + r)*C1_ + c0 + threadIdx.x] = tile[threadIdx.x][r];
}

// ================= conv1: 3x3 256->128, BN+SiLU, f32x2, NHWC =================
// 8x8 px tile x 128 oc. 256 threads: py = tid>>5 (row), ocg = tid&31 (4 oc).
// px-paired accumulators (even pairs free from LDS.128), duplicated weight pairs.
// cp.async double-buffered input staging in ci-plane-major smem layout.
__global__ __launch_bounds__(256, 3) void c1_fast() {
    __shared__ float sIn[2][32*PL];
    int tid = threadIdx.x;
    int n = blockIdx.z;
    int by = blockIdx.y * 8, bx = blockIdx.x * 8;
    int py   = tid >> 5;
    int lane = tid & 31;          // ocg for compute, channel for loading
    uint32_t sbase = smem_u32(sIn);

    // loader precompute: pak = ((pixel*256 + lane) << 7) | (hy*12 + hx)
    int pak[13]; unsigned ebits = 0, vbits = 0;
    #pragma unroll
    for (int j = 0; j < 13; j++) {
        int p = py + j*8;
        pak[j] = 0;
        if (p < 100) {
            int hy = p / 10, hx = p - hy*10;
            int gy = by + hy - 1, gx = bx + hx - 1;
            bool v = (gy >= 0 && gy < H_ && gx >= 0 && gx < W_);
            int pix = v ? (n*HW_ + gy*W_ + gx) : 0;
            pak[j] = ((pix*256 + lane) << 7) | (hy*12 + hx);
            ebits |= 1u << j;
            if (v) vbits |= 1u << j;
        }
    }

    // issue async loads of one ci-chunk into buffer b
    auto load_chunk = [&](int cc, int b) {
        uint32_t soff0 = sbase + (uint32_t)(b * 32 * PL + lane * PL) * 4u;
        #pragma unroll
        for (int j = 0; j < 13; j++) {
            if (ebits >> j & 1) {
                uint32_t sa = soff0 + (uint32_t)(pak[j] & 127) * 4u;
                uint32_t sz = (vbits >> j & 1) ? 4u : 0u;
                cp4(sa, g_xn + (pak[j] >> 7) + cc, sz);
            }
        }
        asm volatile("cp.async.commit_group;");
    };

    load_chunk(0, 0);
    asm volatile("cp.async.wait_group 0;");
    __syncthreads();

    ull acc[4][4];                 // [px pair][oc]
    #pragma unroll
    for (int i = 0; i < 4; i++)
        #pragma unroll
        for (int o = 0; o < 4; o++) acc[i][o] = 0ull;

    int buf = 0;
    for (int cc = 0; cc < C1_; cc += 32) {
        if (cc + 32 < C1_) load_chunk(cc + 32, buf ^ 1);

        #pragma unroll 2
        for (int ci = 0; ci < 32; ci++) {
            const float* plane = &sIn[buf][ci * PL];
            size_t wb = (size_t)(cc + ci) * 2304 + (size_t)lane * 8;
            #pragma unroll
            for (int ky = 0; ky < 3; ky++) {
                const float* row = plane + (py + ky) * 12;
                ulonglong2 t0 = *(const ulonglong2*)row;        // (x0,x1)(x2,x3)
                ulonglong2 t1 = *(const ulonglong2*)(row + 4);  // (x4,x5)(x6,x7)
                ull u0 = t0.x, u1 = t0.y, u2 = t1.x, u3 = t1.y;
                ull u4 = *(const ull*)(row + 8);                // (x8,x9)
                float2 f0 = upk2(u0), f1 = upk2(u1), f2 = upk2(u2),
                       f3 = upk2(u3), f4 = upk2(u4);
                ull o0 = pk2(f0.y, f1.x), o1 = pk2(f1.y, f2.x);
                ull o2 = pk2(f2.y, f3.x), o3 = pk2(f3.y, f4.x);
                #pragma unroll
                for (int kx = 0; kx < 3; kx++) {
                    const ulonglong2* wp = (const ulonglong2*)&g_w1d[wb + (size_t)(ky*3 + kx)*256];
                    ulonglong2 wA = wp[0], wB = wp[1];   // dup pairs oc0,oc1,oc2,oc3
                    ull p0, p1, p2, p3;
                    if (kx == 0)      { p0 = u0; p1 = u1; p2 = u2; p3 = u3; }
                    else if (kx == 1) { p0 = o0; p1 = o1; p2 = o2; p3 = o3; }
                    else              { p0 = u1; p1 = u2; p2 = u3; p3 = u4; }
                    fma2(acc[0][0], p0, wA.x); fma2(acc[0][1], p0, wA.y);
                    fma2(acc[0][2], p0, wB.x); fma2(acc[0][3], p0, wB.y);
                    fma2(acc[1][0], p1, wA.x); fma2(acc[1][1], p1, wA.y);
                    fma2(acc[1][2], p1, wB.x); fma2(acc[1][3], p1, wB.y);
                    fma2(acc[2][0], p2, wA.x); fma2(acc[2][1], p2, wA.y);
                    fma2(acc[2][2], p2, wB.x); fma2(acc[2][3], p2, wB.y);
                    fma2(acc[3][0], p3, wA.x); fma2(acc[3][1], p3, wA.y);
                    fma2(acc[3][2], p3, wB.x); fma2(acc[3][3], p3, wB.y);
                }
            }
        }

        if (cc + 32 < C1_) asm volatile("cp.async.wait_group 0;");
        __syncthreads();
        buf ^= 1;
    }

    // epilogue: bias + SiLU -> NHWC
    float bia[4];
    #pragma unroll
    for (int o = 0; o < 4; o++) bia[o] = g_b1f[lane*4 + o];
    int gy = by + py;
    #pragma unroll
    for (int j = 0; j < 4; j++) {
        float2 v0 = upk2(acc[j][0]), v1 = upk2(acc[j][1]),
               v2 = upk2(acc[j][2]), v3 = upk2(acc[j][3]);
        float4 ra, rb;
        ra.x = silu_f(v0.x + bia[0]); rb.x = silu_f(v0.y + bia[0]);
        ra.y = silu_f(v1.x + bia[1]); rb.y = silu_f(v1.y + bia[1]);
        ra.z = silu_f(v2.x + bia[2]); rb.z = silu_f(v2.y + bia[2]);
        ra.w = silu_f(v3.x + bia[3]); rb.w = silu_f(v3.y + bia[3]);
        size_t base = (size_t)(n*HW_ + gy*W_ + bx + 2*j)*CH_ + lane*4;
        *(float4*)&g_y1[base]       = ra;
        *(float4*)&g_y1[base + CH_] = rb;
    }
}

// ================= GEMM: out[M,256] = A[M,KD] @ B[KD,256] (+epilogue) =================
// MODE 0 (conv2):  A=g_y1  B=g_w2t  bias=g_b2f  SiLU -> g_y2
// MODE 1 (inproj): A=g_y2  B=g_inwt bias=ext    none -> g_xproj
// MODE 2 (outproj):A=g_dcn B=g_outwt bias=g_obf SiLU+resid -> ext out (NCHW)
template<int KD, int MODE>
__global__ __launch_bounds__(256) void gm(const float* __restrict__ bias_ext,
                                          float* __restrict__ out_ext,
                                          const float* __restrict__ resid_ext) {
    const float* A    = (MODE == 0) ? g_y1  : (MODE == 1 ? g_y2   : g_dcn);
    const float* B    = (MODE == 0) ? g_w2t : (MODE == 1 ? g_inwt : g_outwt);
    const float* bias = (MODE == 0) ? g_b2f : (MODE == 1 ? bias_ext : g_obf);
    float* C          = (MODE == 0) ? g_y2  : (MODE == 1 ? g_xproj : out_ext);

    __shared__ float As[16][68];
    __shared__ float Bs[16][136];
    int tid = threadIdx.x;
    int tx = tid & 15, ty = tid >> 4;
    int m0 = blockIdx.x * 64, n0 = blockIdx.y * 128;

    ull acc[4][4];
    #pragma unroll
    for (int i = 0; i < 4; i++)
        #pragma unroll
        for (int j = 0; j < 4; j++) acc[i][j] = 0ull;

    int ar = tid >> 2, ak = (tid & 3) * 4;
    int bk = tid >> 4, bn = (tid & 15) * 8;

    for (int k0 = 0; k0 < KD; k0 += 16) {
        float4 av = *(const float4*)&A[(size_t)(m0 + ar)*KD + k0 + ak];
        const float4* bp = (const float4*)&B[(size_t)(k0 + bk)*256 + n0 + bn];
        float4 bv0 = bp[0], bv1 = bp[1];
        As[ak+0][ar] = av.x; As[ak+1][ar] = av.y;
        As[ak+2][ar] = av.z; As[ak+3][ar] = av.w;
        *(float4*)&Bs[bk][bn]     = bv0;
        *(float4*)&Bs[bk][bn + 4] = bv1;
        __syncthreads();
        #pragma unroll
        for (int k = 0; k < 16; k++) {
            float4 a4 = *(const float4*)&As[k][ty*4];
            ull b[4];
            #pragma unroll
            for (int j = 0; j < 4; j++)
                b[j] = *(const ull*)&Bs[k][tx*8 + 2*j];
            ull ad0 = pk2(a4.x, a4.x), ad1 = pk2(a4.y, a4.y);
            ull ad2 = pk2(a4.z, a4.z), ad3 = pk2(a4.w, a4.w);
            #pragma unroll
            for (int j = 0; j < 4; j++) {
                fma2(acc[0][j], ad0, b[j]);
                fma2(acc[1][j], ad1, b[j]);
                fma2(acc[2][j], ad2, b[j]);
                fma2(acc[3][j], ad3, b[j]);
            }
        }
        __syncthreads();
    }

    #pragma unroll
    for (int i = 0; i < 4; i++) {
        int m = m0 + ty*4 + i;
        int nimg = m / HW_;
        int pp   = m - nimg*HW_;
        #pragma unroll
        for (int j = 0; j < 4; j++) {
            float2 v = upk2(acc[i][j]);
            int nn = n0 + tx*8 + 2*j;
            float r0 = v.x + bias[nn];
            float r1 = v.y + bias[nn+1];
            if (MODE == 0 || MODE == 2) { r0 = silu_f(r0); r1 = silu_f(r1); }
            if (MODE <= 1) {
                C[(size_t)m*256 + nn]     = r0;
                C[(size_t)m*256 + nn + 1] = r1;
            } else {
                size_t base = (size_t)(nimg*256 + nn)*HW_ + pp;
                C[base]       = resid_ext[base]       + r0;
                C[base + HW_] = resid_ext[base + HW_] + r1;
            }
        }
    }
}

// ================= depthwise 3x3 + bias + LayerNorm + GELU =================
__global__ __launch_bounds__(256) void p_dwlngelu(const float* __restrict__ dww,
                                                  const float* __restrict__ dwb,
                                                  const float* __restrict__ lng,
                                                  const float* __restrict__ lnb) {
    int p = blockIdx.x;
    int n = p / HW_, pp = p - n*HW_;
    int y = pp / W_, xx = pp - y*W_;
    int c = threadIdx.x;

    float acc = 0.0f;
    for (int ky = 0; ky < 3; ky++) {
        int gy = y + ky - 1;
        if (gy < 0 || gy >= H_) continue;
        for (int kx = 0; kx < 3; kx++) {
            int gx = xx + kx - 1;
            if (gx < 0 || gx >= W_) continue;
            acc += g_y2[(size_t)(n*HW_ + gy*W_ + gx)*C2_ + c] * dww[c*9 + ky*3 + kx];
        }
    }
    acc += dwb[c];

    __shared__ float red[8], red2[8];
    float v = acc;
    #pragma unroll
    for (int o = 16; o; o >>= 1) v += __shfl_xor_sync(0xffffffffu, v, o);
    if ((c & 31) == 0) red[c >> 5] = v;
    __syncthreads();
    float tot = 0.0f;
    #pragma unroll
    for (int i = 0; i < 8; i++) tot += red[i];
    float mu = tot * (1.0f/256.0f);

    float d = acc - mu;
    float v2 = d*d;
    #pragma unroll
    for (int o = 16; o; o >>= 1) v2 += __shfl_xor_sync(0xffffffffu, v2, o);
    if ((c & 31) == 0) red2[c >> 5] = v2;
    __syncthreads();
    float tot2 = 0.0f;
    #pragma unroll
    for (int i = 0; i < 8; i++) tot2 += red2[i];
    float var = tot2 * (1.0f/256.0f);

    float outv = d * rsqrtf(var + 1e-6f) * lng[c] + lnb[c];
    float gel = 0.5f * outv * (1.0f + erff(outv * 0.70710678118654752f));
    g_dw[(size_t)p*C2_ + c] = gel;
}

// ================= offset + mask heads =================
__global__ __launch_bounds__(256) void p_offmask(const float* __restrict__ offw,
                                                 const float* __restrict__ offb,
                                                 const float* __restrict__ mskw,
                                                 const float* __restrict__ mskb) {
    int p = blockIdx.x;
    int tid = threadIdx.x;
    int warp = tid >> 5, lane = tid & 31;
    __shared__ float sdw[256];
    __shared__ float sres[27];

    sdw[tid] = g_dw[(size_t)p*C2_ + tid];
    __syncthreads();

    for (int r = warp; r < 27; r += 8) {
        const float* wr = (r < 18) ? (offw + r*256) : (mskw + (r-18)*256);
        float s = 0.0f;
        for (int c = lane; c < 256; c += 32) s += sdw[c] * wr[c];
        #pragma unroll
        for (int o = 16; o; o >>= 1) s += __shfl_xor_sync(0xffffffffu, s, o);
        if (lane == 0) sres[r] = s;
    }
    __syncthreads();

    if (tid < 18) g_off[(size_t)p*18 + tid] = sres[tid] + offb[tid];
    if (tid == 0) {
        float l[9], mx = -1e30f;
        #pragma unroll
        for (int k = 0; k < 9; k++) { l[k] = sres[18+k] + mskb[k]; mx = fmaxf(mx, l[k]); }
        float se = 0.0f;
        #pragma unroll
        for (int k = 0; k < 9; k++) { l[k] = expf(l[k] - mx); se += l[k]; }
        float inv = 1.0f / se;
        #pragma unroll
        for (int k = 0; k < 9; k++) g_msk[(size_t)p*9 + k] = l[k]*inv;
    }
}

// ================= DCNv3 core =================
__global__ __launch_bounds__(256) void p_dcn() {
    int p = blockIdx.x;
    int n = p / HW_, pp = p - n*HW_;
    int y = pp / W_, xx = pp - y*W_;
    int c = threadIdx.x;

    __shared__ float sw[9][4];
    __shared__ int   sx0[9], sy0[9];
    if (threadIdx.x < 9) {
        int k = threadIdx.x;
        float m  = g_msk[(size_t)p*9 + k];
        float ox = g_off[(size_t)p*18 + 2*k];
        float oy = g_off[(size_t)p*18 + 2*k + 1];
        float px = (float)xx + (float)(k/3) + ox;     // padded coords
        float py = (float)y  + (float)(k%3) + oy;
        float x0f = floorf(px), y0f = floorf(py);
        float lw = px - x0f, lh = py - y0f;
        sw[k][0] = m * (1.0f - lh) * (1.0f - lw);
        sw[k][1] = m * (1.0f - lh) * lw;
        sw[k][2] = m * lh * (1.0f - lw);
        sw[k][3] = m * lh * lw;
        sx0[k] = (int)x0f;
        sy0[k] = (int)y0f;
    }
    __syncthreads();

    const float* Xb = &g_xproj[(size_t)n * HW_ * C2_];
    float acc = 0.0f;
    for (int k = 0; k < 9; k++) {
        int x0 = sx0[k], y0 = sy0[k];
        #pragma unroll
        for (int t = 0; t < 4; t++) {
            int xi = x0 + (t & 1);
            int yi = y0 + (t >> 1);
            if (xi >= 1 && xi <= W_ && yi >= 1 && yi <= H_) {
                float val = Xb[(size_t)((yi-1)*W_ + (xi-1))*C2_ + c];
                acc = fmaf(sw[k][t], val, acc);
            }
        }
    }
    g_dcn[(size_t)p*C2_ + c] = acc;
}

// ---------------- launch ----------------
extern "C" void kernel_launch(void* const* d_in, const int* in_sizes, int n_in,
                              void* d_out, int out_size) {
    const float* x     = (const float*)d_in[0];
    const float* w1    = (const float*)d_in[1];
    const float* g1    = (const float*)d_in[2];
    const float* b1    = (const float*)d_in[3];
    const float* m1    = (const float*)d_in[4];
    const float* v1    = (const float*)d_in[5];
    const float* w2    = (const float*)d_in[6];
    const float* g2    = (const float*)d_in[7];
    const float* b2    = (const float*)d_in[8];
    const float* m2    = (const float*)d_in[9];
    const float* v2    = (const float*)d_in[10];
    const float* dw_w  = (const float*)d_in[11];
    const float* dw_b  = (const float*)d_in[12];
    const float* ln_g  = (const float*)d_in[13];
    const float* ln_b  = (const float*)d_in[14];
    const float* off_w = (const float*)d_in[15];
    const float* off_b = (const float*)d_in[16];
    const float* msk_w = (const float*)d_in[17];
    const float* msk_b = (const float*)d_in[18];
    const float* in_w  = (const float*)d_in[19];
    const float* in_b  = (const float*)d_in[20];
    const float* out_w = (const float*)d_in[21];
    const float* out_b = (const float*)d_in[22];
    const float* g3    = (const float*)d_in[23];
    const float* b3    = (const float*)d_in[24];
    const float* m3    = (const float*)d_in[25];
    const float* v3    = (const float*)d_in[26];
    float* out = (float*)d_out;

    pk_w1<<<(C1_*9*CH_ + 255)/256, 256>>>(w1, g1, b1, m1, v1);
    pk_lin<<<(C2_*C2_ + 255)/256, 256>>>(w2, g2, b2, m2, v2, in_w, out_w, out_b,
                                         g3, b3, m3, v3);
    k_tr<<<dim3(HW_/32, C1_/32, N_), dim3(32, 8)>>>(x);
    c1_fast<<<dim3(W_/8, H_/8, N_), 256>>>();
    gm<128, 0><<<dim3(M_/64, 2), 256>>>(nullptr, nullptr, nullptr);
    p_dwlngelu<<<M_, 256>>>(dw_w, dw_b, ln_g, ln_b);
    p_offmask<<<M_, 256>>>(off_w, off_b, msk_w, msk_b);
    gm<256, 1><<<dim3(M_/64, 2), 256>>>(in_b, nullptr, nullptr);
    p_dcn<<<M_, 256>>>();
    gm<256, 2><<<dim3(M_/64, 2), 256>>>(nullptr, out, x);
}

// round 8
// speedup vs baseline: 4.5845x; 1.0610x over previous
#include <cuda_runtime.h>
#include <cuda_bf16.h>
#include <math.h>
#include <stdint.h>

// ---------------- problem constants ----------------
#define N_   4
#define C1_  256
#define C2_  256
#define CH_  128
#define H_   80
#define W_   80
#define HW_  6400
#define M_   (N_*HW_)      // 25600 pixels total

// conv1 tile
#define TW   16
#define TH   4
#define RS   20            // halo row stride (18 cols + pad)
#define PL2  (6*RS)        // 120 floats per ci plane

// ---------------- scratch (referenced ONLY inside device code!) ----------------
__device__ float g_xn[M_*C1_];        // x in NHWC
__device__ float g_w1d[C1_*9*CH_*2];  // conv1 w, [ci][kk][oc] BN-folded, duplicated pairs
__device__ float g_b1f[CH_];
__device__ float g_w2t[CH_*C2_];      // conv2 w transposed [k][o], BN-folded
__device__ float g_b2f[C2_];
__device__ float g_inwt[C2_*C2_];     // in_w transposed [k][o]
__device__ float g_outwt[C2_*C2_];    // out_w transposed [k][o], BN3-folded
__device__ float g_obf[C2_];          // folded output bias
__device__ float g_y1[M_*CH_];        // conv1 out NHWC
__device__ float g_y2[M_*C2_];        // conv2 out NHWC
__device__ float g_dw[M_*C2_];        // dw+LN+GELU out NHWC
__device__ float g_xproj[M_*C2_];     // input_proj out NHWC
__device__ float g_dcn[M_*C2_];       // dcn out NHWC
__device__ float g_off[M_*18];
__device__ float g_msk[M_*9];

__device__ __forceinline__ float silu_f(float v) { return v / (1.0f + expf(-v)); }

// ---- f32x2 helpers ----
typedef unsigned long long ull;
__device__ __forceinline__ ull pk2(float lo, float hi) {
    ull r; asm("mov.b64 %0, {%1, %2};" : "=l"(r) : "f"(lo), "f"(hi)); return r;
}
__device__ __forceinline__ void fma2(ull& d, ull a, ull b) {
    asm("fma.rn.f32x2 %0, %1, %2, %0;" : "+l"(d) : "l"(a), "l"(b));
}
__device__ __forceinline__ float2 upk2(ull v) {
    float2 r; asm("mov.b64 {%0, %1}, %2;" : "=f"(r.x), "=f"(r.y) : "l"(v)); return r;
}
__device__ __forceinline__ uint32_t smem_u32(const void* p) {
    uint32_t a;
    asm("{ .reg .u64 t; cvta.to.shared.u64 t, %1; cvt.u32.u64 %0, t; }" : "=r"(a) : "l"(p));
    return a;
}
__device__ __forceinline__ void cp4(uint32_t sa, const float* ga, uint32_t sz) {
    asm volatile("cp.async.ca.shared.global [%0], [%1], 4, %2;\n"
                 :: "r"(sa), "l"(ga), "r"(sz));
}

// ================= pack kernels =================
__global__ void pk_w1(const float* __restrict__ w1, const float* __restrict__ g1,
                      const float* __restrict__ b1, const float* __restrict__ m1,
                      const float* __restrict__ v1) {
    int i = blockIdx.x * blockDim.x + threadIdx.x;
    if (i >= C1_*9*CH_) return;
    int oc = i & (CH_-1);
    int kidx = i >> 7;          // ci*9 + kk
    int ci = kidx / 9, kk = kidx - ci*9;
    float s = g1[oc] * rsqrtf(v1[oc] + 1e-5f);
    float val = w1[(size_t)(oc*C1_ + ci)*9 + kk] * s;
    g_w1d[(size_t)i*2]     = val;
    g_w1d[(size_t)i*2 + 1] = val;
    if (i < CH_) g_b1f[i] = b1[i] - m1[i]*s;
}

__global__ void pk_lin(const float* __restrict__ w2, const float* __restrict__ g2,
                       const float* __restrict__ b2, const float* __restrict__ m2,
                       const float* __restrict__ v2, const float* __restrict__ inw,
                       const float* __restrict__ outw, const float* __restrict__ outb,
                       const float* __restrict__ g3, const float* __restrict__ b3,
                       const float* __restrict__ m3, const float* __restrict__ v3) {
    int i = blockIdx.x * blockDim.x + threadIdx.x;
    if (i >= C2_*C2_) return;
    int o = i & 255, k = i >> 8;
    g_inwt[i] = inw[(size_t)o*C2_ + k];
    float s3 = g3[o] * rsqrtf(v3[o] + 1e-5f);
    g_outwt[i] = outw[(size_t)o*C2_ + k] * s3;
    if (k < CH_) {
        float s2 = g2[o] * rsqrtf(v2[o] + 1e-5f);
        g_w2t[(size_t)k*C2_ + o] = w2[(size_t)o*CH_ + k] * s2;
    }
    if (i < C2_) {
        float s2 = g2[i] * rsqrtf(v2[i] + 1e-5f);
        g_b2f[i] = b2[i] - m2[i]*s2;
        float s3b = g3[i] * rsqrtf(v3[i] + 1e-5f);
        g_obf[i] = outb[i]*s3b + b3[i] - m3[i]*s3b;
    }
}

// ================= NCHW -> NHWC transpose =================
__global__ void k_tr(const float* __restrict__ x) {
    __shared__ float tile[32][33];
    int n  = blockIdx.z;
    int c0 = blockIdx.y * 32, p0 = blockIdx.x * 32;
    for (int r = threadIdx.y; r < 32; r += 8)
        tile[r][threadIdx.x] = x[(size_t)(n*C1_ + c0 + r)*HW_ + p0 + threadIdx.x];
    __syncthreads();
    for (int r = threadIdx.y; r < 32; r += 8)
        g_xn[(size_t)(n*HW_ + p0 + r)*C1_ + c0 + threadIdx.x] = tile[threadIdx.x][r];
}

// ================= conv1: 3x3 256->128, BN+SiLU, f32x2, NHWC =================
// Tile 4 rows x 16 cols. Block 128 thr: py = tid>>5 (warp-uniform row), ocg = tid&31.
// Thread: 8 px-pairs x 4 oc {2ocg, 2ocg+1, 2ocg+64, 2ocg+65} (warp-contiguous weight LDG).
// Input rows broadcast from smem (warp-uniform); cp.async double-buffered.
__global__ __launch_bounds__(128, 3) void c1_fast() {
    __shared__ float sIn[2][32*PL2];
    int tid = threadIdx.x;
    int n = blockIdx.z;
    int by = blockIdx.y * TH, bx = blockIdx.x * TW;
    int py   = tid >> 5;           // 0..3
    int ocg  = tid & 31;
    uint32_t sbase = smem_u32(sIn);

    // loader: thread handles ci = ocg, pixels i = py + 4j (halo 6x18 = 108 px)
    auto load_chunk = [&](int cc, int b) {
        uint32_t s0 = sbase + (uint32_t)((b*32 + ocg) * PL2) * 4u;
        int i = py;
        #pragma unroll
        for (int j = 0; j < 27; j++) {
            int row = i / 18, col = i - row*18;
            int gy = by + row - 1, gx = bx + col - 1;
            bool v = (gy >= 0 && gy < H_ && gx >= 0 && gx < W_);
            const float* ga = g_xn + (size_t)(v ? (n*HW_ + gy*W_ + gx) : 0)*C1_ + cc + ocg;
            cp4(s0 + (uint32_t)(row*RS + col)*4u, ga, v ? 4u : 0u);
            i += 4;
        }
        asm volatile("cp.async.commit_group;");
    };

    load_chunk(0, 0);
    asm volatile("cp.async.wait_group 0;");
    __syncthreads();

    ull acc[8][4];                 // [px pair][oc slot]
    #pragma unroll
    for (int j = 0; j < 8; j++)
        #pragma unroll
        for (int o = 0; o < 4; o++) acc[j][o] = 0ull;

    int buf = 0;
    for (int cc = 0; cc < C1_; cc += 32) {
        if (cc + 32 < C1_) load_chunk(cc + 32, buf ^ 1);

        #pragma unroll 1
        for (int ci = 0; ci < 32; ci++) {
            const float* plane = &sIn[buf][ci * PL2];
            const float* wb = &g_w1d[(size_t)((cc + ci)*9)*256 + ocg*4];
            #pragma unroll
            for (int ky = 0; ky < 3; ky++) {
                const float* row = plane + (py + ky) * RS;
                ulonglong2 a0 = *(const ulonglong2*)row;        // u0,u1
                ulonglong2 a1 = *(const ulonglong2*)(row + 4);  // u2,u3
                ulonglong2 a2 = *(const ulonglong2*)(row + 8);  // u4,u5
                ulonglong2 a3 = *(const ulonglong2*)(row + 12); // u6,u7
                ull u[9] = {a0.x, a0.y, a1.x, a1.y, a2.x, a2.y, a3.x, a3.y,
                            *(const ull*)(row + 16)};
                ull o[8];
                #pragma unroll
                for (int j = 0; j < 8; j++) {
                    float2 lo = upk2(u[j]), hi = upk2(u[j+1]);
                    o[j] = pk2(lo.y, hi.x);
                }
                #pragma unroll
                for (int kx = 0; kx < 3; kx++) {
                    const float* wk = wb + (ky*3 + kx)*256;
                    ulonglong2 wlo = *(const ulonglong2*)wk;          // oc 2ocg, 2ocg+1
                    ulonglong2 whi = *(const ulonglong2*)(wk + 128);  // oc 2ocg+64, +65
                    #pragma unroll
                    for (int j = 0; j < 8; j++) {
                        ull p = (kx == 0) ? u[j] : (kx == 1 ? o[j] : u[j+1]);
                        fma2(acc[j][0], p, wlo.x);
                        fma2(acc[j][1], p, wlo.y);
                        fma2(acc[j][2], p, whi.x);
                        fma2(acc[j][3], p, whi.y);
                    }
                }
            }
        }

        if (cc + 32 < C1_) asm volatile("cp.async.wait_group 0;");
        __syncthreads();
        buf ^= 1;
    }

    // epilogue: bias + SiLU -> NHWC. oc set {2ocg, 2ocg+1, 2ocg+64, 2ocg+65}
    int oc0 = ocg * 2;
    float b0 = g_b1f[oc0], b1 = g_b1f[oc0+1], b2 = g_b1f[oc0+64], b3 = g_b1f[oc0+65];
    int gy = by + py;
    size_t rowbase = (size_t)(n*HW_ + gy*W_ + bx)*CH_;
    #pragma unroll
    for (int j = 0; j < 8; j++) {
        float2 v0 = upk2(acc[j][0]), v1 = upk2(acc[j][1]);
        float2 v2 = upk2(acc[j][2]), v3 = upk2(acc[j][3]);
        size_t pb0 = rowbase + (size_t)(2*j)*CH_;
        size_t pb1 = pb0 + CH_;
        float2 e0 = {silu_f(v0.x + b0), silu_f(v1.x + b1)};
        float2 e1 = {silu_f(v2.x + b2), silu_f(v3.x + b3)};
        float2 f0 = {silu_f(v0.y + b0), silu_f(v1.y + b1)};
        float2 f1 = {silu_f(v2.y + b2), silu_f(v3.y + b3)};
        *(float2*)&g_y1[pb0 + oc0]      = e0;
        *(float2*)&g_y1[pb0 + oc0 + 64] = e1;
        *(float2*)&g_y1[pb1 + oc0]      = f0;
        *(float2*)&g_y1[pb1 + oc0 + 64] = f1;
    }
}

// ================= GEMM: out[M,256] = A[M,KD] @ B[KD,256] (+epilogue) =================
// MODE 0 (conv2):  A=g_y1  B=g_w2t  bias=g_b2f  SiLU -> g_y2
// MODE 1 (inproj): A=g_y2  B=g_inwt bias=ext    none -> g_xproj
// MODE 2 (outproj):A=g_dcn B=g_outwt bias=g_obf SiLU+resid -> ext out (NCHW)
template<int KD, int MODE>
__global__ __launch_bounds__(256) void gm(const float* __restrict__ bias_ext,
                                          float* __restrict__ out_ext,
                                          const float* __restrict__ resid_ext) {
    const float* A    = (MODE == 0) ? g_y1  : (MODE == 1 ? g_y2   : g_dcn);
    const float* B    = (MODE == 0) ? g_w2t : (MODE == 1 ? g_inwt : g_outwt);
    const float* bias = (MODE == 0) ? g_b2f : (MODE == 1 ? bias_ext : g_obf);
    float* C          = (MODE == 0) ? g_y2  : (MODE == 1 ? g_xproj : out_ext);

    __shared__ float As[16][68];
    __shared__ float Bs[16][136];
    int tid = threadIdx.x;
    int tx = tid & 15, ty = tid >> 4;
    int m0 = blockIdx.x * 64, n0 = blockIdx.y * 128;

    ull acc[4][4];
    #pragma unroll
    for (int i = 0; i < 4; i++)
        #pragma unroll
        for (int j = 0; j < 4; j++) acc[i][j] = 0ull;

    int ar = tid >> 2, ak = (tid & 3) * 4;
    int bk = tid >> 4, bn = (tid & 15) * 8;

    for (int k0 = 0; k0 < KD; k0 += 16) {
        float4 av = *(const float4*)&A[(size_t)(m0 + ar)*KD + k0 + ak];
        const float4* bp = (const float4*)&B[(size_t)(k0 + bk)*256 + n0 + bn];
        float4 bv0 = bp[0], bv1 = bp[1];
        As[ak+0][ar] = av.x; As[ak+1][ar] = av.y;
        As[ak+2][ar] = av.z; As[ak+3][ar] = av.w;
        *(float4*)&Bs[bk][bn]     = bv0;
        *(float4*)&Bs[bk][bn + 4] = bv1;
        __syncthreads();
        #pragma unroll
        for (int k = 0; k < 16; k++) {
            float4 a4 = *(const float4*)&As[k][ty*4];
            ull b[4];
            #pragma unroll
            for (int j = 0; j < 4; j++)
                b[j] = *(const ull*)&Bs[k][tx*8 + 2*j];
            ull ad0 = pk2(a4.x, a4.x), ad1 = pk2(a4.y, a4.y);
            ull ad2 = pk2(a4.z, a4.z), ad3 = pk2(a4.w, a4.w);
            #pragma unroll
            for (int j = 0; j < 4; j++) {
                fma2(acc[0][j], ad0, b[j]);
                fma2(acc[1][j], ad1, b[j]);
                fma2(acc[2][j], ad2, b[j]);
                fma2(acc[3][j], ad3, b[j]);
            }
        }
        __syncthreads();
    }

    #pragma unroll
    for (int i = 0; i < 4; i++) {
        int m = m0 + ty*4 + i;
        int nimg = m / HW_;
        int pp   = m - nimg*HW_;
        #pragma unroll
        for (int j = 0; j < 4; j++) {
            float2 v = upk2(acc[i][j]);
            int nn = n0 + tx*8 + 2*j;
            float r0 = v.x + bias[nn];
            float r1 = v.y + bias[nn+1];
            if (MODE == 0 || MODE == 2) { r0 = silu_f(r0); r1 = silu_f(r1); }
            if (MODE <= 1) {
                C[(size_t)m*256 + nn]     = r0;
                C[(size_t)m*256 + nn + 1] = r1;
            } else {
                size_t base = (size_t)(nimg*256 + nn)*HW_ + pp;
                C[base]       = resid_ext[base]       + r0;
                C[base + HW_] = resid_ext[base + HW_] + r1;
            }
        }
    }
}

// ================= depthwise 3x3 + bias + LayerNorm + GELU =================
__global__ __launch_bounds__(256) void p_dwlngelu(const float* __restrict__ dww,
                                                  const float* __restrict__ dwb,
                                                  const float* __restrict__ lng,
                                                  const float* __restrict__ lnb) {
    int p = blockIdx.x;
    int n = p / HW_, pp = p - n*HW_;
    int y = pp / W_, xx = pp - y*W_;
    int c = threadIdx.x;

    float acc = 0.0f;
    for (int ky = 0; ky < 3; ky++) {
        int gy = y + ky - 1;
        if (gy < 0 || gy >= H_) continue;
        for (int kx = 0; kx < 3; kx++) {
            int gx = xx + kx - 1;
            if (gx < 0 || gx >= W_) continue;
            acc += g_y2[(size_t)(n*HW_ + gy*W_ + gx)*C2_ + c] * dww[c*9 + ky*3 + kx];
        }
    }
    acc += dwb[c];

    __shared__ float red[8], red2[8];
    float v = acc;
    #pragma unroll
    for (int o = 16; o; o >>= 1) v += __shfl_xor_sync(0xffffffffu, v, o);
    if ((c & 31) == 0) red[c >> 5] = v;
    __syncthreads();
    float tot = 0.0f;
    #pragma unroll
    for (int i = 0; i < 8; i++) tot += red[i];
    float mu = tot * (1.0f/256.0f);

    float d = acc - mu;
    float v2 = d*d;
    #pragma unroll
    for (int o = 16; o; o >>= 1) v2 += __shfl_xor_sync(0xffffffffu, v2, o);
    if ((c & 31) == 0) red2[c >> 5] = v2;
    __syncthreads();
    float tot2 = 0.0f;
    #pragma unroll
    for (int i = 0; i < 8; i++) tot2 += red2[i];
    float var = tot2 * (1.0f/256.0f);

    float outv = d * rsqrtf(var + 1e-6f) * lng[c] + lnb[c];
    float gel = 0.5f * outv * (1.0f + erff(outv * 0.70710678118654752f));
    g_dw[(size_t)p*C2_ + c] = gel;
}

// ================= offset + mask heads (weights cached in smem, 32 px/block) ========
__global__ __launch_bounds__(256) void p_offmask2(const float* __restrict__ offw,
                                                  const float* __restrict__ offb,
                                                  const float* __restrict__ mskw,
                                                  const float* __restrict__ mskb) {
    __shared__ float wsm[27*256];
    __shared__ float sdw[256];
    __shared__ float sres[27];
    int tid = threadIdx.x;
    int warp = tid >> 5, lane = tid & 31;

    #pragma unroll
    for (int i = tid; i < 27*256; i += 256) {
        int r = i >> 8, c = i & 255;
        wsm[i] = (r < 18) ? offw[r*256 + c] : mskw[(r - 18)*256 + c];
    }
    __syncthreads();

    int p0 = blockIdx.x * 32;
    for (int pi = 0; pi < 32; pi++) {
        int p = p0 + pi;
        sdw[tid] = g_dw[(size_t)p*256 + tid];
        __syncthreads();
        for (int r = warp; r < 27; r += 8) {
            const float* wr = &wsm[r*256];
            float s = 0.0f;
            #pragma unroll
            for (int k = 0; k < 8; k++) s += sdw[lane + 32*k] * wr[lane + 32*k];
            #pragma unroll
            for (int o = 16; o; o >>= 1) s += __shfl_xor_sync(0xffffffffu, s, o);
            if (lane == 0) sres[r] = s;
        }
        __syncthreads();
        if (tid < 18) g_off[(size_t)p*18 + tid] = sres[tid] + offb[tid];
        if (tid == 0) {
            float l[9], mx = -1e30f;
            #pragma unroll
            for (int k = 0; k < 9; k++) { l[k] = sres[18+k] + mskb[k]; mx = fmaxf(mx, l[k]); }
            float se = 0.0f;
            #pragma unroll
            for (int k = 0; k < 9; k++) { l[k] = expf(l[k] - mx); se += l[k]; }
            float inv = 1.0f / se;
            #pragma unroll
            for (int k = 0; k < 9; k++) g_msk[(size_t)p*9 + k] = l[k]*inv;
        }
    }
}

// ================= DCNv3 core =================
__global__ __launch_bounds__(256) void p_dcn() {
    int p = blockIdx.x;
    int n = p / HW_, pp = p - n*HW_;
    int y = pp / W_, xx = pp - y*W_;
    int c = threadIdx.x;

    __shared__ float sw[9][4];
    __shared__ int   sx0[9], sy0[9];
    if (threadIdx.x < 9) {
        int k = threadIdx.x;
        float m  = g_msk[(size_t)p*9 + k];
        float ox = g_off[(size_t)p*18 + 2*k];
        float oy = g_off[(size_t)p*18 + 2*k + 1];
        float px = (float)xx + (float)(k/3) + ox;     // padded coords
        float py = (float)y  + (float)(k%3) + oy;
        float x0f = floorf(px), y0f = floorf(py);
        float lw = px - x0f, lh = py - y0f;
        sw[k][0] = m * (1.0f - lh) * (1.0f - lw);
        sw[k][1] = m * (1.0f - lh) * lw;
        sw[k][2] = m * lh * (1.0f - lw);
        sw[k][3] = m * lh * lw;
        sx0[k] = (int)x0f;
        sy0[k] = (int)y0f;
    }
    __syncthreads();

    const float* Xb = &g_xproj[(size_t)n * HW_ * C2_];
    float acc = 0.0f;
    for (int k = 0; k < 9; k++) {
        int x0 = sx0[k], y0 = sy0[k];
        #pragma unroll
        for (int t = 0; t < 4; t++) {
            int xi = x0 + (t & 1);
            int yi = y0 + (t >> 1);
            if (xi >= 1 && xi <= W_ && yi >= 1 && yi <= H_) {
                float val = Xb[(size_t)((yi-1)*W_ + (xi-1))*C2_ + c];
                acc = fmaf(sw[k][t], val, acc);
            }
        }
    }
    g_dcn[(size_t)p*C2_ + c] = acc;
}

// ---------------- launch ----------------
extern "C" void kernel_launch(void* const* d_in, const int* in_sizes, int n_in,
                              void* d_out, int out_size) {
    const float* x     = (const float*)d_in[0];
    const float* w1    = (const float*)d_in[1];
    const float* g1    = (const float*)d_in[2];
    const float* b1    = (const float*)d_in[3];
    const float* m1    = (const float*)d_in[4];
    const float* v1    = (const float*)d_in[5];
    const float* w2    = (const float*)d_in[6];
    const float* g2    = (const float*)d_in[7];
    const float* b2    = (const float*)d_in[8];
    const float* m2    = (const float*)d_in[9];
    const float* v2    = (const float*)d_in[10];
    const float* dw_w  = (const float*)d_in[11];
    const float* dw_b  = (const float*)d_in[12];
    const float* ln_g  = (const float*)d_in[13];
    const float* ln_b  = (const float*)d_in[14];
    const float* off_w = (const float*)d_in[15];
    const float* off_b = (const float*)d_in[16];
    const float* msk_w = (const float*)d_in[17];
    const float* msk_b = (const float*)d_in[18];
    const float* in_w  = (const float*)d_in[19];
    const float* in_b  = (const float*)d_in[20];
    const float* out_w = (const float*)d_in[21];
    const float* out_b = (const float*)d_in[22];
    const float* g3    = (const float*)d_in[23];
    const float* b3    = (const float*)d_in[24];
    const float* m3    = (const float*)d_in[25];
    const float* v3    = (const float*)d_in[26];
    float* out = (float*)d_out;

    pk_w1<<<(C1_*9*CH_ + 255)/256, 256>>>(w1, g1, b1, m1, v1);
    pk_lin<<<(C2_*C2_ + 255)/256, 256>>>(w2, g2, b2, m2, v2, in_w, out_w, out_b,
                                         g3, b3, m3, v3);
    k_tr<<<dim3(HW_/32, C1_/32, N_), dim3(32, 8)>>>(x);
    c1_fast<<<dim3(W_/TW, H_/TH, N_), 128>>>();
    gm<128, 0><<<dim3(M_/64, 2), 256>>>(nullptr, nullptr, nullptr);
    p_dwlngelu<<<M_, 256>>>(dw_w, dw_b, ln_g, ln_b);
    p_offmask2<<<M_/32, 256>>>(off_w, off_b, msk_w, msk_b);
    gm<256, 1><<<dim3(M_/64, 2), 256>>>(in_b, nullptr, nullptr);
    p_dcn<<<M_, 256>>>();
    gm<256, 2><<<dim3(M_/64, 2), 256>>>(nullptr, out, x);
}